// round 7
// baseline (speedup 1.0000x reference)
#include <cuda_runtime.h>
#include <cstdint>

#define NQ   4
#define DIM  16
#define NC   4
#define BLK  256
#define WARPS_PER_BLK 8
#define GRID 148
#define WARPS_TOTAL (GRID * WARPS_PER_BLK)      // 1184
#define GROUP_ROWS 32
#define CHUNK_ROWS 8
#define ROW_PITCH 592                           // 148 words; conflict-free LDS.128
#define CHUNK_BYTES (CHUNK_ROWS * ROW_PITCH)    // 4736
#define NBUF 4
#define WARP_SMEM (NBUF * CHUNK_BYTES)          // 18944
#define SMEM_BYTES (WARPS_PER_BLK * WARP_SMEM)  // 151552
#define MAX_G 7                                 // ceil(8192 / 1184)

__device__ double g_acc[8];
__device__ float  g_scale[NC];
__device__ float  g_shift[NC];
__device__ unsigned g_cnt;
__device__ int g_flag;

__global__ void k_init() {
    if (threadIdx.x < 8) g_acc[threadIdx.x] = 0.0;
    if (threadIdx.x == 0) { g_cnt = 0u; g_flag = 0; }
}

__device__ __forceinline__ void cp16(char* dst_smem, const float4* src) {
    unsigned d = (unsigned)__cvta_generic_to_shared(dst_smem);
    asm volatile("cp.async.cg.shared.global [%0], [%1], 16;\n" :: "r"(d), "l"(src));
}
__device__ __forceinline__ void cp_commit() { asm volatile("cp.async.commit_group;\n"); }
template<int N> __device__ __forceinline__ void cp_wait() {
    asm volatile("cp.async.wait_group %0;\n" :: "n"(N));
}

// 8-row chunk = 288 float4, 9 coalesced cp.async per lane
__device__ __forceinline__ void issue_chunk8(char* dst, const float* x, size_t sampleRow, int lane) {
    const float4* src = (const float4*)(x + sampleRow * 144);
    #pragma unroll
    for (int k = 0; k < 9; k++) {
        const int r0  = (32 * k) / 36;
        const int rem = (32 * k) % 36;
        int ge  = (lane + rem) >= 36;
        int row = r0 + ge;
        int p   = lane + rem - (ge ? 36 : 0);
        cp16(dst + (uint32_t)row * ROW_PITCH + ((uint32_t)p << 4), src + lane + 32 * k);
    }
    cp_commit();
}

// issue all 4 chunks (one commit each) of a 32-row group
__device__ __forceinline__ void issue_group(char* wbuf, const float* x, size_t rowbase, int lane) {
    #pragma unroll
    for (int c = 0; c < NBUF; c++)
        issue_chunk8(wbuf + c * CHUNK_BYTES, x, rowbase + (size_t)c * CHUNK_ROWS, lane);
}

// lane l -> sample row (l&7), quarter (l>>3); partial (left,right) over 3 image rows
__device__ __forceinline__ void pool8(const char* cbase, int lane, float& oL, float& oR) {
    int r = lane & 7, q = lane >> 3;
    const char* rb = cbase + (uint32_t)r * ROW_PITCH + (uint32_t)q * 144u;
    float a0 = 0.f, a1 = 0.f;
    #pragma unroll
    for (int j = 0; j < 9; j++) {
        float4 v = *(const float4*)(rb + 16 * j);
        int pos = j % 3;
        if (pos == 0)      { a0 += v.x + v.y + v.z + v.w; }
        else if (pos == 1) { a0 += v.x + v.y; a1 += v.z + v.w; }
        else               { a1 += v.x + v.y + v.z + v.w; }
    }
    oL = a0; oR = a1;
}

__global__ void __launch_bounds__(BLK, 1) k_persist(
    const float* __restrict__ x,
    const float* __restrict__ wts,
    const float* __restrict__ W,
    const float* __restrict__ bias,
    const float* __restrict__ gamma,
    const float* __restrict__ beta,
    float* __restrict__ out,
    int B, float invB)
{
    extern __shared__ char sbuf[];
    const int t = threadIdx.x;
    const int lane = t & 31;
    const int wid  = t >> 5;
    const int gw   = blockIdx.x * WARPS_PER_BLK + wid;
    char* wbuf = sbuf + wid * WARP_SMEM;

    const int totalGroups = B / GROUP_ROWS;     // 8192

    float wc[8], ws[8];
    #pragma unroll
    for (int i = 0; i < 8; i++) __sincosf(wts[i] * 0.5f, &ws[i], &wc[i]);

    float lg[MAX_G][4];
    float sum0=0.f,sum1=0.f,sum2=0.f,sum3=0.f, sq0=0.f,sq1=0.f,sq2=0.f,sq3=0.f;

    // prologue: burst-issue entire first group (4 commits in flight)
    if (gw < totalGroups)
        issue_group(wbuf, x, (size_t)gw * GROUP_ROWS, lane);

    #pragma unroll 1
    for (int kg = 0; kg < MAX_G; kg++) {
        int g = gw + kg * WARPS_TOTAL;
        if (g >= totalGroups) break;
        int gn = g + WARPS_TOTAL;

        // drain & pool the 4 chunks of this group
        float L[4], R[4];
        cp_wait<3>(); __syncwarp(); pool8(wbuf + 0 * CHUNK_BYTES, lane, L[0], R[0]);
        cp_wait<2>(); __syncwarp(); pool8(wbuf + 1 * CHUNK_BYTES, lane, L[1], R[1]);
        cp_wait<1>(); __syncwarp(); pool8(wbuf + 2 * CHUNK_BYTES, lane, L[2], R[2]);
        cp_wait<0>(); __syncwarp(); pool8(wbuf + 3 * CHUNK_BYTES, lane, L[3], R[3]);
        __syncwarp();

        // burst-issue the entire NEXT group before computing (keeps DRAM fed)
        if (gn < totalGroups)
            issue_group(wbuf, x, (size_t)gn * GROUP_ROWS, lane);

        // butterfly: quarters -> top/bottom halves
        float tL[4], tR[4];
        #pragma unroll
        for (int c = 0; c < 4; c++) {
            tL[c] = L[c] + __shfl_xor_sync(0xFFFFFFFFu, L[c], 8);
            tR[c] = R[c] + __shfl_xor_sync(0xFFFFFFFFu, R[c], 8);
        }
        int rl = lane & 7;
        float s0 = 0.f, s1 = 0.f, s2 = 0.f, s3 = 0.f;
        #pragma unroll
        for (int c = 0; c < 4; c++) {
            float v0 = __shfl_sync(0xFFFFFFFFu, tL[c], rl);        // top-left
            float v1 = __shfl_sync(0xFFFFFFFFu, tR[c], rl);        // top-right
            float v2 = __shfl_sync(0xFFFFFFFFu, tL[c], rl + 16);   // bottom-left
            float v3 = __shfl_sync(0xFFFFFFFFu, tR[c], rl + 16);   // bottom-right
            if ((lane >> 3) == c) { s0 = v0; s1 = v1; s2 = v2; s3 = v3; }
        }

        // ---- circuit ----
        const float inv72 = 1.f / 72.f;
        float pc4[4], ps4[4];
        __sincosf(s0 * inv72, &ps4[0], &pc4[0]);
        __sincosf(s1 * inv72, &ps4[1], &pc4[1]);
        __sincosf(s2 * inv72, &ps4[2], &pc4[2]);
        __sincosf(s3 * inv72, &ps4[3], &pc4[3]);

        float re[DIM], im[DIM];
        #pragma unroll
        for (int k = 0; k < DIM; k++) {
            float m = ((k & 8) ? ps4[0] : pc4[0])
                    * ((k & 4) ? ps4[1] : pc4[1])
                    * ((k & 2) ? ps4[2] : pc4[2])
                    * ((k & 1) ? ps4[3] : pc4[3]);
            int pc = __popc(k) & 3;
            re[k] = (pc == 0) ? m : ((pc == 2) ? -m : 0.f);
            im[k] = (pc == 1) ? -m : ((pc == 3) ? m : 0.f);
        }
        int idx = 0;
        #pragma unroll
        for (int d = 0; d < 2; d++) {
            #pragma unroll
            for (int w = 0; w < NQ; w++) {
                float cc = wc[idx], ss = ws[idx]; idx++;
                int bit = 1 << (3 - w);
                #pragma unroll
                for (int k = 0; k < DIM; k++) {
                    if (!(k & bit)) {
                        int k1 = k | bit;
                        float r0 = re[k], r1 = re[k1];
                        re[k]  = cc * r0 - ss * r1;
                        re[k1] = ss * r0 + cc * r1;
                        float i0 = im[k], i1 = im[k1];
                        im[k]  = cc * i0 - ss * i1;
                        im[k1] = ss * i0 + cc * i1;
                    }
                }
            }
            #pragma unroll
            for (int k = 0; k < DIM; k++) {
                int par = (((k >> 3) & (k >> 2)) ^ ((k >> 2) & (k >> 1)) ^ ((k >> 1) & k)) & 1;
                if (par) { re[k] = -re[k]; im[k] = -im[k]; }
            }
        }
        float q0=0.f, q1=0.f, q2=0.f, q3=0.f;
        #pragma unroll
        for (int k = 0; k < DIM; k++) {
            float p = re[k] * re[k] + im[k] * im[k];
            q0 += (k & 8) ? -p : p;
            q1 += (k & 4) ? -p : p;
            q2 += (k & 2) ? -p : p;
            q3 += (k & 1) ? -p : p;
        }
        #pragma unroll
        for (int c2 = 0; c2 < NC; c2++) {
            lg[kg][c2] = __ldg(&bias[c2])
                       + q0 * __ldg(&W[c2*4+0]) + q1 * __ldg(&W[c2*4+1])
                       + q2 * __ldg(&W[c2*4+2]) + q3 * __ldg(&W[c2*4+3]);
        }
        sum0 += lg[kg][0]; sum1 += lg[kg][1]; sum2 += lg[kg][2]; sum3 += lg[kg][3];
        sq0 += lg[kg][0]*lg[kg][0]; sq1 += lg[kg][1]*lg[kg][1];
        sq2 += lg[kg][2]*lg[kg][2]; sq3 += lg[kg][3]*lg[kg][3];
    }

    // ---- block reduction ----
    float red[8] = {sum0,sum1,sum2,sum3,sq0,sq1,sq2,sq3};
    #pragma unroll
    for (int off = 16; off > 0; off >>= 1) {
        #pragma unroll
        for (int j = 0; j < 8; j++)
            red[j] += __shfl_down_sync(0xFFFFFFFFu, red[j], off);
    }
    __syncthreads();
    float* rsm = (float*)sbuf;
    if (lane == 0) {
        #pragma unroll
        for (int j = 0; j < 8; j++) rsm[j * WARPS_PER_BLK + wid] = red[j];
    }
    __syncthreads();
    if (t < 8) {
        float acc = 0.f;
        #pragma unroll
        for (int wgi = 0; wgi < WARPS_PER_BLK; wgi++) acc += rsm[t * WARPS_PER_BLK + wgi];
        atomicAdd(&g_acc[t], (double)acc);
        __threadfence();
    }
    __syncthreads();

    // ---- grid barrier (148 blocks, 1/SM, all co-resident) ----
    if (t == 0) {
        unsigned r = atomicAdd(&g_cnt, 1u);
        if (r == gridDim.x - 1u) {
            #pragma unroll
            for (int c2 = 0; c2 < NC; c2++) {
                double m = g_acc[c2] * (double)invB;
                double v = g_acc[4 + c2] * (double)invB - m * m;
                float inv = rsqrtf((float)v + 1e-5f);
                g_scale[c2] = gamma[c2] * inv;
                g_shift[c2] = beta[c2] - (float)m * inv * gamma[c2];
            }
            __threadfence();
            atomicExch(&g_flag, 1);
        } else {
            while (atomicAdd(&g_flag, 0) == 0) __nanosleep(64);
        }
    }
    __syncthreads();

    float sc[4], sh[4];
    #pragma unroll
    for (int c2 = 0; c2 < NC; c2++) {
        sc[c2] = *((volatile float*)&g_scale[c2]);
        sh[c2] = *((volatile float*)&g_shift[c2]);
    }

    // ---- coalesced normalized write ----
    float4* o4 = (float4*)out;
    #pragma unroll
    for (int kg = 0; kg < MAX_G; kg++) {
        int g = gw + kg * WARPS_TOTAL;
        if (g < totalGroups) {
            o4[(size_t)g * GROUP_ROWS + lane] =
                make_float4(lg[kg][0]*sc[0]+sh[0], lg[kg][1]*sc[1]+sh[1],
                            lg[kg][2]*sc[2]+sh[2], lg[kg][3]*sc[3]+sh[3]);
        }
    }
}

extern "C" void kernel_launch(void* const* d_in, const int* in_sizes, int n_in,
                              void* d_out, int out_size) {
    const float* x     = (const float*)d_in[0];
    const float* wts   = (const float*)d_in[1];
    const float* W     = (const float*)d_in[2];
    const float* bias  = (const float*)d_in[3];
    const float* gamma = (const float*)d_in[4];
    const float* beta  = (const float*)d_in[5];
    float* out = (float*)d_out;

    int B = in_sizes[0] / 144;    // 262144

    cudaFuncSetAttribute(k_persist, cudaFuncAttributeMaxDynamicSharedMemorySize, SMEM_BYTES);

    k_init<<<1, 32>>>();
    k_persist<<<GRID, BLK, SMEM_BYTES>>>(x, wts, W, bias, gamma, beta, out,
                                         B, 1.0f / (float)B);
}